// round 14
// baseline (speedup 1.0000x reference)
#include <cuda_runtime.h>
#include <cuda_bf16.h>
#include <cstdint>

#define TT 8192
#define FF 64
#define HH 4096
#define PP 4

// ===========================================================================
// Device scratch (no allocation allowed -> __device__ globals)
// Partials stored TRANSPOSED: [chunk][t] (coalesced reduce reads)
// ===========================================================================
__device__ __align__(16) float g_part[(size_t)64 * TT * 4];    // 8.4 MB (64 chunks)
__device__ __align__(16) float g_p2[8 * TT * 4];               // stage-1 output (8 chunks)
__device__ __align__(16) float g_ybuf[2][TT * 4];              // inter-layer activations
// Split-bf16 copies (plain row-major)
__device__ __align__(16) __nv_bfloat16 g_xh[TT * FF];
__device__ __align__(16) __nv_bfloat16 g_xl[TT * FF];
__device__ __align__(16) __nv_bfloat16 g_wh[3 * HH * FF];
__device__ __align__(16) __nv_bfloat16 g_wl[3 * HH * FF];

__device__ __forceinline__ float tanh_fast(float x) {
    float y;
    asm("tanh.approx.f32 %0, %1;" : "=f"(y) : "f"(x));
    return y;
}
__device__ __forceinline__ float sig_fast(float x) {
    return 0.5f * tanh_fast(0.5f * x) + 0.5f;
}
__device__ __forceinline__ void dot4(float& acc, const float4 wv, const float4 xv) {
    acc = fmaf(wv.x, xv.x, acc);
    acc = fmaf(wv.y, xv.y, acc);
    acc = fmaf(wv.z, xv.z, acc);
    acc = fmaf(wv.w, xv.w, acc);
}

// bf16 HMMA m16n8k16 (baseline PTX feature -> compiles on compute_103)
__device__ __forceinline__ void mma16816(float d[4],
                                         uint32_t a0, uint32_t a1, uint32_t a2, uint32_t a3,
                                         uint32_t b0, uint32_t b1) {
    asm volatile(
        "mma.sync.aligned.m16n8k16.row.col.f32.bf16.bf16.f32 "
        "{%0,%1,%2,%3}, {%4,%5,%6,%7}, {%8,%9}, {%0,%1,%2,%3};"
        : "+f"(d[0]), "+f"(d[1]), "+f"(d[2]), "+f"(d[3])
        : "r"(a0), "r"(a1), "r"(a2), "r"(a3), "r"(b0), "r"(b1));
}

union BF8 { __nv_bfloat16 h[8]; uint4 v; };

__device__ __forceinline__ void cvt8(const float* src, uint4& hv, uint4& lv) {
    BF8 hb, lb;
#pragma unroll
    for (int j = 0; j < 8; j++) {
        const float v = src[j];
        const __nv_bfloat16 h = __float2bfloat16(v);
        hb.h[j] = h;
        lb.h[j] = __float2bfloat16(v - __bfloat162float(h));
    }
    hv = hb.v; lv = lb.v;
}

__global__ __launch_bounds__(256)
void conv_w2(const float* __restrict__ Wih)
{
    const int idx = blockIdx.x * 256 + threadIdx.x;  // < 3*4096*8
    const int s = idx >> 15;
    const int r9 = idx & 32767;
    const int n = r9 >> 3;
    const int u = r9 & 7;
    const int gbrow = (s == 0) ? 0 : (s == 1) ? 2 * HH : 3 * HH;
    uint4 hv, lv;
    cvt8(Wih + (size_t)(gbrow + n) * FF + u * 8, hv, lv);
    const size_t o = (size_t)(s * HH + n) * 8 + u;
    ((uint4*)g_wh)[o] = hv;
    ((uint4*)g_wl)[o] = lv;
}

__global__ __launch_bounds__(256)
void conv_x2(const float* __restrict__ X)
{
    const int idx = blockIdx.x * 256 + threadIdx.x;  // < 8192*8
    const int t = idx >> 3, u = idx & 7;
    uint4 hv, lv;
    cvt8(X + (size_t)t * FF + u * 8, hv, lv);
    ((uint4*)g_xh)[(size_t)t * 8 + u] = hv;
    ((uint4*)g_xl)[(size_t)t * 8 + u] = lv;
}

// ---------------------------------------------------------------------------
// Layer 0 via mma.sync bf16 (split hi/lo, 3 passes).
// Block: 128 t x 64 n, 256 threads = 8 warps of 32t x 32n.
// __launch_bounds__(256) WITHOUT min-blocks: R12's (256,2) capped ptxas at
// 128 regs while the warp tile needs ~170 -> ~40 regs/thread spilled, eating
// the entire L2-traffic win. 1 CTA/SM (smem 86KB nearly forces it anyway).
// ---------------------------------------------------------------------------
#define OFF_XSL  16384
#define OFF_WSH  32768
#define OFF_WSL  57344
#define OFF_BIAS 81920
#define OFF_WHR  82688
#define OFF_RED  83712
#define L0_SMEM  86016

__global__ __launch_bounds__(256)
void l0_mma(const float* __restrict__ bih,
            const float* __restrict__ bhh,
            const float* __restrict__ Whr)
{
    extern __shared__ __align__(128) char smem[];
    char* cxh = smem;
    char* cxl = smem + OFF_XSL;
    char* cwh = smem + OFF_WSH;
    char* cwl = smem + OFF_WSL;
    float (*bias_s)[64] = (float(*)[64])(smem + OFF_BIAS);
    float (*whr_s)[64]  = (float(*)[64])(smem + OFF_WHR);
    float4 (*red_s)[32] = (float4(*)[32])(smem + OFF_RED);

    const int tid  = threadIdx.x;
    const int wt   = tid >> 5;
    const int tg   = wt >> 1;           // t quarter (32 rows of 128)
    const int ng   = wt & 1;            // n half (32 cols of 64)
    const int lane = tid & 31;
    const int g5   = lane >> 2;
    const int tid4 = lane & 3;
    const int t0   = blockIdx.x * 128;
    const int n0   = blockIdx.y * 64;

    // ---- stage x tile (128 rows x 8 units) x {hi,lo}, swizzled ----
    {
        const uint4* sxh = (const uint4*)g_xh + (size_t)t0 * 8;
        const uint4* sxl = (const uint4*)g_xl + (size_t)t0 * 8;
#pragma unroll
        for (int it = 0; it < 4; it++) {
            const int i = tid + 256 * it;          // 0..1023
            const int r = i >> 3, u = i & 7;
            const int d = r * 8 + (u ^ (r & 7));
            ((uint4*)cxh)[d] = sxh[i];
            ((uint4*)cxl)[d] = sxl[i];
        }
    }
    // ---- stage W tiles (3 gates x 64 rows x 8 units) x {hi,lo}, swizzled ----
    {
#pragma unroll
        for (int it = 0; it < 6; it++) {
            const int i = tid + 256 * it;          // 0..1535
            const int s = i >> 9;
            const int rem = i & 511;
            const int n = rem >> 3, u = rem & 7;
            const size_t src = (size_t)(s * HH + n0 + n) * 8 + u;
            const int d = (s * 64 + n) * 8 + (u ^ (n & 7));
            ((uint4*)cwh)[d] = ((const uint4*)g_wh)[src];
            ((uint4*)cwl)[d] = ((const uint4*)g_wl)[src];
        }
    }
    if (tid < 64) {
        const int nn = n0 + tid;
        bias_s[0][tid] = bih[nn] + bhh[nn];
        bias_s[1][tid] = bih[2 * HH + nn] + bhh[2 * HH + nn];
        bias_s[2][tid] = bih[3 * HH + nn] + bhh[3 * HH + nn];
#pragma unroll
        for (int p = 0; p < 4; p++) whr_s[p][tid] = Whr[(size_t)p * HH + nn];
    }
    __syncthreads();

    // Accumulators: [t-set s][n-subtile j][gate][frag]
    float d[2][4][3][4];
#pragma unroll
    for (int s = 0; s < 2; s++)
#pragma unroll
        for (int j = 0; j < 4; j++)
#pragma unroll
            for (int g = 0; g < 3; g++)
#pragma unroll
                for (int e = 0; e < 4; e++) d[s][j][g][e] = 0.f;

#pragma unroll
    for (int ks = 0; ks < 4; ks++) {
        const int kb0 = ks * 32 + tid4 * 4;
        const int kb1 = kb0 + 16;

        uint32_t ah[2][4], al[2][4];
#pragma unroll
        for (int s = 0; s < 2; s++) {
            const int r0 = tg * 32 + s * 16 + g5;
            const int r1 = r0 + 8;
            const int x0 = (r0 & 7) << 4;
            const int x1 = (r1 & 7) << 4;
            ah[s][0] = *(const uint32_t*)(cxh + r0 * 128 + (kb0 ^ x0));
            ah[s][1] = *(const uint32_t*)(cxh + r1 * 128 + (kb0 ^ x1));
            ah[s][2] = *(const uint32_t*)(cxh + r0 * 128 + (kb1 ^ x0));
            ah[s][3] = *(const uint32_t*)(cxh + r1 * 128 + (kb1 ^ x1));
            al[s][0] = *(const uint32_t*)(cxl + r0 * 128 + (kb0 ^ x0));
            al[s][1] = *(const uint32_t*)(cxl + r1 * 128 + (kb0 ^ x1));
            al[s][2] = *(const uint32_t*)(cxl + r0 * 128 + (kb1 ^ x0));
            al[s][3] = *(const uint32_t*)(cxl + r1 * 128 + (kb1 ^ x1));
        }

#pragma unroll
        for (int g = 0; g < 3; g++) {
#pragma unroll
            for (int j = 0; j < 4; j++) {
                const int nrow = ng * 32 + j * 8 + g5;
                const int roff = (g * 64 + nrow) * 128;
                const int xrn = (nrow & 7) << 4;
                const uint32_t bh0 = *(const uint32_t*)(cwh + roff + (kb0 ^ xrn));
                const uint32_t bh1 = *(const uint32_t*)(cwh + roff + (kb1 ^ xrn));
                const uint32_t bl0 = *(const uint32_t*)(cwl + roff + (kb0 ^ xrn));
                const uint32_t bl1 = *(const uint32_t*)(cwl + roff + (kb1 ^ xrn));
#pragma unroll
                for (int s = 0; s < 2; s++) {
                    mma16816(d[s][j][g], ah[s][0], ah[s][1], ah[s][2], ah[s][3], bh0, bh1);
                    mma16816(d[s][j][g], ah[s][0], ah[s][1], ah[s][2], ah[s][3], bl0, bl1);
                    mma16816(d[s][j][g], al[s][0], al[s][1], al[s][2], al[s][3], bh0, bh1);
                }
            }
        }
    }

    // ---- epilogue: bias + LSTM cell + W_hr projection ----
    float hs[2][2][4];      // [s][row-half][p]
#pragma unroll
    for (int s = 0; s < 2; s++)
#pragma unroll
        for (int r = 0; r < 2; r++)
#pragma unroll
            for (int p = 0; p < 4; p++) hs[s][r][p] = 0.f;

#pragma unroll
    for (int s = 0; s < 2; s++) {
#pragma unroll
        for (int j = 0; j < 4; j++) {
#pragma unroll
            for (int e = 0; e < 4; e++) {
                const int rh = e >> 1, c = e & 1;
                const int nl = ng * 32 + j * 8 + tid4 * 2 + c;
                const float gi = d[s][j][0][e] + bias_s[0][nl];
                const float gg = d[s][j][1][e] + bias_s[1][nl];
                const float go = d[s][j][2][e] + bias_s[2][nl];
                const float cc = sig_fast(gi) * tanh_fast(gg);
                const float h  = sig_fast(go) * tanh_fast(cc);
#pragma unroll
                for (int p = 0; p < 4; p++)
                    hs[s][rh][p] = fmaf(h, whr_s[p][nl], hs[s][rh][p]);
            }
        }
    }

    // quad reduce -> per (t-row, warp) sum over its 32 n-cols
#pragma unroll
    for (int off = 1; off <= 2; off <<= 1)
#pragma unroll
        for (int s = 0; s < 2; s++)
#pragma unroll
            for (int r = 0; r < 2; r++)
#pragma unroll
                for (int p = 0; p < 4; p++)
                    hs[s][r][p] += __shfl_xor_sync(0xffffffffu, hs[s][r][p], off);

    // cross-ng fold in smem: ng=0 deposits, ng=1 adds and writes out
    if (ng == 0 && tid4 == 0) {
#pragma unroll
        for (int s = 0; s < 2; s++)
#pragma unroll
            for (int r = 0; r < 2; r++) {
                const int row = s * 16 + g5 + r * 8;     // 0..31
                red_s[tg][row] = make_float4(hs[s][r][0], hs[s][r][1],
                                             hs[s][r][2], hs[s][r][3]);
            }
    }
    __syncthreads();
    if (ng == 1 && tid4 == 0) {
#pragma unroll
        for (int s = 0; s < 2; s++)
#pragma unroll
            for (int r = 0; r < 2; r++) {
                const int row = s * 16 + g5 + r * 8;
                const float4 o = red_s[tg][row];
                const int tgl = t0 + tg * 32 + row;
                ((float4*)g_part)[(size_t)blockIdx.y * TT + tgl] =
                    make_float4(hs[s][r][0] + o.x, hs[s][r][1] + o.y,
                                hs[s][r][2] + o.z, hs[s][r][3] + o.w);
            }
    }
}

// Stage 1: fold 64 chunks -> 8. Grid (TT/256, 8), 256 thr. Coalesced.
__global__ __launch_bounds__(256)
void reduce_stage1()
{
    const int t  = blockIdx.x * 256 + threadIdx.x;
    const int cg = blockIdx.y;
    const float4* p = (const float4*)g_part;
    float4 s = make_float4(0.f, 0.f, 0.f, 0.f);
#pragma unroll
    for (int c = cg * 8; c < cg * 8 + 8; c++) {
        const float4 v = p[(size_t)c * TT + t];
        s.x += v.x; s.y += v.y; s.z += v.z; s.w += v.w;
    }
    ((float4*)g_p2)[(size_t)cg * TT + t] = s;
}

// ---------------------------------------------------------------------------
// Layers 1/2 (K=4): one thread = one timestep. Hidden split 8-way.
// Grid (TT/128, 8). Writes transposed partials [chunk][t].
// ---------------------------------------------------------------------------
__global__ __launch_bounds__(128)
void l12_gemm(int xsel,
              const float* __restrict__ Wih,
              const float* __restrict__ bih,
              const float* __restrict__ bhh,
              const float* __restrict__ Whr)
{
    const float* __restrict__ Y = g_ybuf[xsel];

    __shared__ float4 wsg[3][128];
    __shared__ float4 wrs[128];
    __shared__ float4 bss[128];

    const int tid = threadIdx.x;
    const int t   = blockIdx.x * 128 + tid;
    const int h0  = blockIdx.y * (HH / 8);

    const float4 y = ((const float4*)Y)[t];
    float a0 = 0.f, a1 = 0.f, a2 = 0.f, a3 = 0.f;

    const int gg[3] = {0, 2, 3};
    for (int tile = 0; tile < HH / 8; tile += 128) {
        __syncthreads();
        const int hr = h0 + tile + tid;
#pragma unroll
        for (int g = 0; g < 3; g++)
            wsg[g][tid] = ((const float4*)Wih)[gg[g] * HH + hr];
        {
            float4 wv;
            wv.x = Whr[0 * HH + hr];
            wv.y = Whr[1 * HH + hr];
            wv.z = Whr[2 * HH + hr];
            wv.w = Whr[3 * HH + hr];
            wrs[tid] = wv;
            float4 bv;
            bv.x = bih[hr] + bhh[hr];
            bv.y = bih[2 * HH + hr] + bhh[2 * HH + hr];
            bv.z = bih[3 * HH + hr] + bhh[3 * HH + hr];
            bv.w = 0.f;
            bss[tid] = bv;
        }
        __syncthreads();

#pragma unroll 4
        for (int r = 0; r < 128; r++) {
            const float4 wi = wsg[0][r];
            const float4 wg = wsg[1][r];
            const float4 wo = wsg[2][r];
            const float4 b  = bss[r];
            const float4 w  = wrs[r];
            float gi = b.x; dot4(gi, wi, y);
            float gv = b.y; dot4(gv, wg, y);
            float go = b.z; dot4(go, wo, y);
            const float c = sig_fast(gi) * tanh_fast(gv);
            const float h = sig_fast(go) * tanh_fast(c);
            a0 = fmaf(h, w.x, a0);
            a1 = fmaf(h, w.y, a1);
            a2 = fmaf(h, w.z, a2);
            a3 = fmaf(h, w.w, a3);
        }
    }

    ((float4*)g_part)[(size_t)blockIdx.y * TT + t] = make_float4(a0, a1, a2, a3);
}

// Final fold of NCH transposed chunks -> [T,4].  src: 0 = g_part, 1 = g_p2
template <int NCH>
__global__ void reduce_part_k(float* __restrict__ dext, int dsel, int ssel)
{
    float* dst = (dsel < 0) ? dext : g_ybuf[dsel];
    const float* src = ssel ? g_p2 : g_part;
    const int t = blockIdx.x * blockDim.x + threadIdx.x;
    if (t >= TT) return;
    const float4* p = (const float4*)src;
    float4 s = make_float4(0.f, 0.f, 0.f, 0.f);
#pragma unroll
    for (int c = 0; c < NCH; c++) {
        const float4 v = p[(size_t)c * TT + t];
        s.x += v.x; s.y += v.y; s.z += v.z; s.w += v.w;
    }
    ((float4*)dst)[t] = s;
}

extern "C" void kernel_launch(void* const* d_in, const int* in_sizes, int n_in,
                              void* d_out, int out_size)
{
    (void)in_sizes; (void)n_in; (void)out_size;

    const float* x    = (const float*)d_in[0];
    const float* Wih0 = (const float*)d_in[1];
    const float* bih0 = (const float*)d_in[3];
    const float* bhh0 = (const float*)d_in[4];
    const float* Whr0 = (const float*)d_in[5];
    const float* Wih1 = (const float*)d_in[6];
    const float* bih1 = (const float*)d_in[8];
    const float* bhh1 = (const float*)d_in[9];
    const float* Whr1 = (const float*)d_in[10];
    const float* Wih2 = (const float*)d_in[11];
    const float* bih2 = (const float*)d_in[13];
    const float* bhh2 = (const float*)d_in[14];
    const float* Whr2 = (const float*)d_in[15];
    float* out = (float*)d_out;

    cudaFuncSetAttribute(l0_mma, cudaFuncAttributeMaxDynamicSharedMemorySize, L0_SMEM);

    // Pre-convert to split-bf16
    conv_w2<<<384, 256>>>(Wih0);
    conv_x2<<<256, 256>>>(x);

    // Layer 0: tensor cores (mma.sync) + fused epilogue, two-stage reduce
    l0_mma<<<dim3(64, 64), 256, L0_SMEM>>>(bih0, bhh0, Whr0);
    reduce_stage1<<<dim3(TT / 256, 8), 256>>>();
    reduce_part_k<8><<<TT / 256, 256>>>(nullptr, 0, 1);

    // Layer 1
    l12_gemm<<<dim3(TT / 128, 8), 128>>>(0, Wih1, bih1, bhh1, Whr1);
    reduce_part_k<8><<<TT / 256, 256>>>(nullptr, 1, 0);
    // Layer 2
    l12_gemm<<<dim3(TT / 128, 8), 128>>>(1, Wih2, bih2, bhh2, Whr2);
    reduce_part_k<8><<<TT / 256, 256>>>(out, -1, 0);
}

// round 15
// speedup vs baseline: 1.8137x; 1.8137x over previous
#include <cuda_runtime.h>
#include <cuda_bf16.h>
#include <cstdint>

#define TT 8192
#define FF 64
#define HH 4096
#define PP 4

// ===========================================================================
// Device scratch (no allocation allowed -> __device__ globals)
// Partials stored TRANSPOSED: [chunk][t] (coalesced reduce reads)
// ===========================================================================
__device__ __align__(16) float g_part[(size_t)128 * TT * 4];   // 16.8 MB (128 chunks)
__device__ __align__(16) float g_p2[8 * TT * 4];               // stage-1 output (8 chunks)
__device__ __align__(16) float g_ybuf[2][TT * 4];              // inter-layer activations
// Split-bf16 copies (plain row-major)
__device__ __align__(16) __nv_bfloat16 g_xh[TT * FF];
__device__ __align__(16) __nv_bfloat16 g_xl[TT * FF];
__device__ __align__(16) __nv_bfloat16 g_wh[3 * HH * FF];
__device__ __align__(16) __nv_bfloat16 g_wl[3 * HH * FF];

__device__ __forceinline__ float tanh_fast(float x) {
    float y;
    asm("tanh.approx.f32 %0, %1;" : "=f"(y) : "f"(x));
    return y;
}
__device__ __forceinline__ float sig_fast(float x) {
    return 0.5f * tanh_fast(0.5f * x) + 0.5f;
}
__device__ __forceinline__ void dot4(float& acc, const float4 wv, const float4 xv) {
    acc = fmaf(wv.x, xv.x, acc);
    acc = fmaf(wv.y, xv.y, acc);
    acc = fmaf(wv.z, xv.z, acc);
    acc = fmaf(wv.w, xv.w, acc);
}
__device__ __forceinline__ uint32_t smem_u32(const void* p) {
    uint32_t a;
    asm("{ .reg .u64 t; cvta.to.shared.u64 t, %1; cvt.u32.u64 %0, t; }"
        : "=r"(a) : "l"(p));
    return a;
}

// bf16 HMMA m16n8k16 (baseline PTX feature)
__device__ __forceinline__ void mma16816(float d[4],
                                         uint32_t a0, uint32_t a1, uint32_t a2, uint32_t a3,
                                         uint32_t b0, uint32_t b1) {
    asm volatile(
        "mma.sync.aligned.m16n8k16.row.col.f32.bf16.bf16.f32 "
        "{%0,%1,%2,%3}, {%4,%5,%6,%7}, {%8,%9}, {%0,%1,%2,%3};"
        : "+f"(d[0]), "+f"(d[1]), "+f"(d[2]), "+f"(d[3])
        : "r"(a0), "r"(a1), "r"(a2), "r"(a3), "r"(b0), "r"(b1));
}
__device__ __forceinline__ void ldsm_x4(uint32_t r[4], uint32_t addr) {
    asm volatile("ldmatrix.sync.aligned.m8n8.x4.shared.b16 {%0,%1,%2,%3}, [%4];"
                 : "=r"(r[0]), "=r"(r[1]), "=r"(r[2]), "=r"(r[3]) : "r"(addr));
}
__device__ __forceinline__ void ldsm_x2(uint32_t& r0, uint32_t& r1, uint32_t addr) {
    asm volatile("ldmatrix.sync.aligned.m8n8.x2.shared.b16 {%0,%1}, [%2];"
                 : "=r"(r0), "=r"(r1) : "r"(addr));
}

union BF8 { __nv_bfloat16 h[8]; uint4 v; };

__device__ __forceinline__ void cvt8(const float* src, uint4& hv, uint4& lv) {
    BF8 hb, lb;
#pragma unroll
    for (int j = 0; j < 8; j++) {
        const float v = src[j];
        const __nv_bfloat16 h = __float2bfloat16(v);
        hb.h[j] = h;
        lb.h[j] = __float2bfloat16(v - __bfloat162float(h));
    }
    hv = hb.v; lv = lb.v;
}

__global__ __launch_bounds__(256)
void conv_w2(const float* __restrict__ Wih)
{
    const int idx = blockIdx.x * 256 + threadIdx.x;  // < 3*4096*8
    const int s = idx >> 15;
    const int r9 = idx & 32767;
    const int n = r9 >> 3;
    const int u = r9 & 7;
    const int gbrow = (s == 0) ? 0 : (s == 1) ? 2 * HH : 3 * HH;
    uint4 hv, lv;
    cvt8(Wih + (size_t)(gbrow + n) * FF + u * 8, hv, lv);
    const size_t o = (size_t)(s * HH + n) * 8 + u;
    ((uint4*)g_wh)[o] = hv;
    ((uint4*)g_wl)[o] = lv;
}

__global__ __launch_bounds__(256)
void conv_x2(const float* __restrict__ X)
{
    const int idx = blockIdx.x * 256 + threadIdx.x;  // < 8192*8
    const int t = idx >> 3, u = idx & 7;
    uint4 hv, lv;
    cvt8(X + (size_t)t * FF + u * 8, hv, lv);
    ((uint4*)g_xh)[(size_t)t * 8 + u] = hv;
    ((uint4*)g_xl)[(size_t)t * 8 + u] = lv;
}

// ---------------------------------------------------------------------------
// Layer 0 via mma.sync bf16 (split hi/lo, 3 passes) + ldmatrix fragment loads.
// Block: 128 t x 32 n, 256 threads = 8 warps of 32t x 16n (tg = wt>>1, ng = wt&1).
// Warp tile kept small (48 accums, ~100 regs) so (256,2) gives 2 CTAs/SM with
// NO spills (R12 spilled at 96 accums; R14 showed 1 CTA/SM is 2x worse).
// Grid: (64, 128). Smem XOR-swizzle: unit u of row r at u ^ (r&7).
// Smem layout (bytes): xsh 0 (16K) | xsl 16384 (16K) | wsh 32768 (12K)
//   | wsl 45056 (12K) | bias 57344 (384) | whr 57728 (512) | red 58240 (2K)
// ---------------------------------------------------------------------------
#define OFF_XSL  16384
#define OFF_WSH  32768
#define OFF_WSL  45056
#define OFF_BIAS 57344
#define OFF_WHR  57728
#define OFF_RED  58240
#define L0_SMEM  60416

__global__ __launch_bounds__(256, 2)
void l0_mma(const float* __restrict__ bih,
            const float* __restrict__ bhh,
            const float* __restrict__ Whr)
{
    extern __shared__ __align__(128) char smem[];
    char* cxh = smem;
    char* cxl = smem + OFF_XSL;
    char* cwh = smem + OFF_WSH;
    char* cwl = smem + OFF_WSL;
    float (*bias_s)[32] = (float(*)[32])(smem + OFF_BIAS);
    float (*whr_s)[32]  = (float(*)[32])(smem + OFF_WHR);
    float4 (*red_s)[32] = (float4(*)[32])(smem + OFF_RED);

    const int tid  = threadIdx.x;
    const int wt   = tid >> 5;
    const int tg   = wt >> 1;           // t quarter (32 rows of 128)
    const int ng   = wt & 1;            // n half (16 cols of 32)
    const int lane = tid & 31;
    const int g5   = lane >> 2;
    const int tid4 = lane & 3;
    const int t0   = blockIdx.x * 128;
    const int n0   = blockIdx.y * 32;

    // ---- stage x tile (128 rows x 8 units) x {hi,lo}, swizzled ----
    {
        const uint4* sxh = (const uint4*)g_xh + (size_t)t0 * 8;
        const uint4* sxl = (const uint4*)g_xl + (size_t)t0 * 8;
#pragma unroll
        for (int it = 0; it < 4; it++) {
            const int i = tid + 256 * it;          // 0..1023
            const int r = i >> 3, u = i & 7;
            const int d = r * 8 + (u ^ (r & 7));
            ((uint4*)cxh)[d] = sxh[i];
            ((uint4*)cxl)[d] = sxl[i];
        }
    }
    // ---- stage W tiles (3 gates x 32 rows x 8 units) x {hi,lo}, swizzled ----
    {
#pragma unroll
        for (int it = 0; it < 3; it++) {
            const int i = tid + 256 * it;          // 0..767
            const int s = i >> 8;
            const int rem = i & 255;
            const int n = rem >> 3, u = rem & 7;
            const size_t src = (size_t)(s * HH + n0 + n) * 8 + u;
            const int d = (s * 32 + n) * 8 + (u ^ (n & 7));
            ((uint4*)cwh)[d] = ((const uint4*)g_wh)[src];
            ((uint4*)cwl)[d] = ((const uint4*)g_wl)[src];
        }
    }
    if (tid < 32) {
        const int nn = n0 + tid;
        bias_s[0][tid] = bih[nn] + bhh[nn];
        bias_s[1][tid] = bih[2 * HH + nn] + bhh[2 * HH + nn];
        bias_s[2][tid] = bih[3 * HH + nn] + bhh[3 * HH + nn];
#pragma unroll
        for (int p = 0; p < 4; p++) whr_s[p][tid] = Whr[(size_t)p * HH + nn];
    }
    __syncthreads();

    const uint32_t sb_xh = smem_u32(cxh);
    const uint32_t sb_xl = smem_u32(cxl);
    const uint32_t sb_wh = smem_u32(cwh);
    const uint32_t sb_wl = smem_u32(cwl);

    // Accumulators: [t-set s][n-subtile j][gate][frag]  -> 48 floats
    float d[2][2][3][4];
#pragma unroll
    for (int s = 0; s < 2; s++)
#pragma unroll
        for (int j = 0; j < 2; j++)
#pragma unroll
            for (int g = 0; g < 3; g++)
#pragma unroll
                for (int e = 0; e < 4; e++) d[s][j][g][e] = 0.f;

#pragma unroll
    for (int ks = 0; ks < 4; ks++) {
        // A fragments via ldmatrix.x4: lanes 0-15 -> rows (lane&15) of k-lo
        // block, lanes 16-31 -> same rows of k-hi block.
        uint32_t ah[2][4], al[2][4];
#pragma unroll
        for (int s = 0; s < 2; s++) {
            const int row = tg * 32 + s * 16 + (lane & 15);
            const int kb  = ks * 32 + (lane & 16);
            const uint32_t off = (uint32_t)(row * 128 + (kb ^ ((row & 7) << 4)));
            ldsm_x4(ah[s], sb_xh + off);
            ldsm_x4(al[s], sb_xl + off);
        }

#pragma unroll
        for (int g = 0; g < 3; g++) {
#pragma unroll
            for (int j = 0; j < 2; j++) {
                // B fragments via ldmatrix.x2: lanes 0-7 -> n rows at k-lo,
                // lanes 8-15 -> n rows at k-hi.
                const int n  = ng * 16 + j * 8 + (lane & 7);
                const int kb = ks * 32 + ((lane & 8) ? 16 : 0);
                const uint32_t off =
                    (uint32_t)((g * 32 + n) * 128 + (kb ^ ((n & 7) << 4)));
                uint32_t bh0, bh1, bl0, bl1;
                ldsm_x2(bh0, bh1, sb_wh + off);
                ldsm_x2(bl0, bl1, sb_wl + off);
#pragma unroll
                for (int s = 0; s < 2; s++)
                    mma16816(d[s][j][g], ah[s][0], ah[s][1], ah[s][2], ah[s][3], bh0, bh1);
#pragma unroll
                for (int s = 0; s < 2; s++)
                    mma16816(d[s][j][g], ah[s][0], ah[s][1], ah[s][2], ah[s][3], bl0, bl1);
#pragma unroll
                for (int s = 0; s < 2; s++)
                    mma16816(d[s][j][g], al[s][0], al[s][1], al[s][2], al[s][3], bh0, bh1);
            }
        }
    }

    // ---- epilogue: bias + LSTM cell + W_hr projection ----
    float hs[2][2][4];      // [s][row-half][p]
#pragma unroll
    for (int s = 0; s < 2; s++)
#pragma unroll
        for (int r = 0; r < 2; r++)
#pragma unroll
            for (int p = 0; p < 4; p++) hs[s][r][p] = 0.f;

#pragma unroll
    for (int s = 0; s < 2; s++) {
#pragma unroll
        for (int j = 0; j < 2; j++) {
#pragma unroll
            for (int e = 0; e < 4; e++) {
                const int rh = e >> 1, c = e & 1;
                const int nl = ng * 16 + j * 8 + tid4 * 2 + c;
                const float gi = d[s][j][0][e] + bias_s[0][nl];
                const float gg = d[s][j][1][e] + bias_s[1][nl];
                const float go = d[s][j][2][e] + bias_s[2][nl];
                const float cc = sig_fast(gi) * tanh_fast(gg);
                const float h  = sig_fast(go) * tanh_fast(cc);
#pragma unroll
                for (int p = 0; p < 4; p++)
                    hs[s][rh][p] = fmaf(h, whr_s[p][nl], hs[s][rh][p]);
            }
        }
    }

    // quad reduce -> per (t-row, warp) sum over its 16 n-cols
#pragma unroll
    for (int off = 1; off <= 2; off <<= 1)
#pragma unroll
        for (int s = 0; s < 2; s++)
#pragma unroll
            for (int r = 0; r < 2; r++)
#pragma unroll
                for (int p = 0; p < 4; p++)
                    hs[s][r][p] += __shfl_xor_sync(0xffffffffu, hs[s][r][p], off);

    // cross-ng fold in smem: ng=0 deposits, ng=1 adds and writes out
    if (ng == 0 && tid4 == 0) {
#pragma unroll
        for (int s = 0; s < 2; s++)
#pragma unroll
            for (int r = 0; r < 2; r++) {
                const int row = s * 16 + g5 + r * 8;     // 0..31
                red_s[tg][row] = make_float4(hs[s][r][0], hs[s][r][1],
                                             hs[s][r][2], hs[s][r][3]);
            }
    }
    __syncthreads();
    if (ng == 1 && tid4 == 0) {
#pragma unroll
        for (int s = 0; s < 2; s++)
#pragma unroll
            for (int r = 0; r < 2; r++) {
                const int row = s * 16 + g5 + r * 8;
                const float4 o = red_s[tg][row];
                const int tgl = t0 + tg * 32 + row;
                ((float4*)g_part)[(size_t)blockIdx.y * TT + tgl] =
                    make_float4(hs[s][r][0] + o.x, hs[s][r][1] + o.y,
                                hs[s][r][2] + o.z, hs[s][r][3] + o.w);
            }
    }
}

// Stage 1: fold 128 chunks -> 8. Grid (TT/256, 8), 256 thr. Coalesced.
__global__ __launch_bounds__(256)
void reduce_stage1()
{
    const int t  = blockIdx.x * 256 + threadIdx.x;
    const int cg = blockIdx.y;
    const float4* p = (const float4*)g_part;
    float4 s = make_float4(0.f, 0.f, 0.f, 0.f);
#pragma unroll
    for (int c = cg * 16; c < cg * 16 + 16; c++) {
        const float4 v = p[(size_t)c * TT + t];
        s.x += v.x; s.y += v.y; s.z += v.z; s.w += v.w;
    }
    ((float4*)g_p2)[(size_t)cg * TT + t] = s;
}

// ---------------------------------------------------------------------------
// Layers 1/2 (K=4): one thread = one timestep. Hidden split 8-way.
// Grid (TT/128, 8). Writes transposed partials [chunk][t].
// ---------------------------------------------------------------------------
__global__ __launch_bounds__(128)
void l12_gemm(int xsel,
              const float* __restrict__ Wih,
              const float* __restrict__ bih,
              const float* __restrict__ bhh,
              const float* __restrict__ Whr)
{
    const float* __restrict__ Y = g_ybuf[xsel];

    __shared__ float4 wsg[3][128];
    __shared__ float4 wrs[128];
    __shared__ float4 bss[128];

    const int tid = threadIdx.x;
    const int t   = blockIdx.x * 128 + tid;
    const int h0  = blockIdx.y * (HH / 8);

    const float4 y = ((const float4*)Y)[t];
    float a0 = 0.f, a1 = 0.f, a2 = 0.f, a3 = 0.f;

    const int gg[3] = {0, 2, 3};
    for (int tile = 0; tile < HH / 8; tile += 128) {
        __syncthreads();
        const int hr = h0 + tile + tid;
#pragma unroll
        for (int g = 0; g < 3; g++)
            wsg[g][tid] = ((const float4*)Wih)[gg[g] * HH + hr];
        {
            float4 wv;
            wv.x = Whr[0 * HH + hr];
            wv.y = Whr[1 * HH + hr];
            wv.z = Whr[2 * HH + hr];
            wv.w = Whr[3 * HH + hr];
            wrs[tid] = wv;
            float4 bv;
            bv.x = bih[hr] + bhh[hr];
            bv.y = bih[2 * HH + hr] + bhh[2 * HH + hr];
            bv.z = bih[3 * HH + hr] + bhh[3 * HH + hr];
            bv.w = 0.f;
            bss[tid] = bv;
        }
        __syncthreads();

#pragma unroll 4
        for (int r = 0; r < 128; r++) {
            const float4 wi = wsg[0][r];
            const float4 wg = wsg[1][r];
            const float4 wo = wsg[2][r];
            const float4 b  = bss[r];
            const float4 w  = wrs[r];
            float gi = b.x; dot4(gi, wi, y);
            float gv = b.y; dot4(gv, wg, y);
            float go = b.z; dot4(go, wo, y);
            const float c = sig_fast(gi) * tanh_fast(gv);
            const float h = sig_fast(go) * tanh_fast(c);
            a0 = fmaf(h, w.x, a0);
            a1 = fmaf(h, w.y, a1);
            a2 = fmaf(h, w.z, a2);
            a3 = fmaf(h, w.w, a3);
        }
    }

    ((float4*)g_part)[(size_t)blockIdx.y * TT + t] = make_float4(a0, a1, a2, a3);
}

// Final fold of NCH transposed chunks -> [T,4].  src: 0 = g_part, 1 = g_p2
template <int NCH>
__global__ void reduce_part_k(float* __restrict__ dext, int dsel, int ssel)
{
    float* dst = (dsel < 0) ? dext : g_ybuf[dsel];
    const float* src = ssel ? g_p2 : g_part;
    const int t = blockIdx.x * blockDim.x + threadIdx.x;
    if (t >= TT) return;
    const float4* p = (const float4*)src;
    float4 s = make_float4(0.f, 0.f, 0.f, 0.f);
#pragma unroll
    for (int c = 0; c < NCH; c++) {
        const float4 v = p[(size_t)c * TT + t];
        s.x += v.x; s.y += v.y; s.z += v.z; s.w += v.w;
    }
    ((float4*)dst)[t] = s;
}

extern "C" void kernel_launch(void* const* d_in, const int* in_sizes, int n_in,
                              void* d_out, int out_size)
{
    (void)in_sizes; (void)n_in; (void)out_size;

    const float* x    = (const float*)d_in[0];
    const float* Wih0 = (const float*)d_in[1];
    const float* bih0 = (const float*)d_in[3];
    const float* bhh0 = (const float*)d_in[4];
    const float* Whr0 = (const float*)d_in[5];
    const float* Wih1 = (const float*)d_in[6];
    const float* bih1 = (const float*)d_in[8];
    const float* bhh1 = (const float*)d_in[9];
    const float* Whr1 = (const float*)d_in[10];
    const float* Wih2 = (const float*)d_in[11];
    const float* bih2 = (const float*)d_in[13];
    const float* bhh2 = (const float*)d_in[14];
    const float* Whr2 = (const float*)d_in[15];
    float* out = (float*)d_out;

    cudaFuncSetAttribute(l0_mma, cudaFuncAttributeMaxDynamicSharedMemorySize, L0_SMEM);

    // Pre-convert to split-bf16
    conv_w2<<<384, 256>>>(Wih0);
    conv_x2<<<256, 256>>>(x);

    // Layer 0: tensor cores (mma.sync + ldmatrix) + fused epilogue
    l0_mma<<<dim3(64, 128), 256, L0_SMEM>>>(bih0, bhh0, Whr0);
    reduce_stage1<<<dim3(TT / 256, 8), 256>>>();
    reduce_part_k<8><<<TT / 256, 256>>>(nullptr, 0, 1);

    // Layer 1
    l12_gemm<<<dim3(TT / 128, 8), 128>>>(0, Wih1, bih1, bhh1, Whr1);
    reduce_part_k<8><<<TT / 256, 256>>>(nullptr, 1, 0);
    // Layer 2
    l12_gemm<<<dim3(TT / 128, 8), 128>>>(1, Wih2, bih2, bhh2, Whr2);
    reduce_part_k<8><<<TT / 256, 256>>>(out, -1, 0);
}